// round 4
// baseline (speedup 1.0000x reference)
#include <cuda_runtime.h>
#include <cuda_bf16.h>
#include <math.h>
#include <cstdint>

#define B_  4
#define L_  256
#define D_  256
#define P_  32
#define H_  8
#define HD_ 32
#define DH_ 128   // D/2

typedef unsigned long long u64;

// ======================= packed f32x2 helpers ==============================
__device__ __forceinline__ u64 pk2(float lo, float hi) {
    u64 r;
    asm("mov.b64 %0, {%1, %2};" : "=l"(r) : "r"(__float_as_uint(lo)), "r"(__float_as_uint(hi)));
    return r;
}
__device__ __forceinline__ void fma2(u64& d, u64 a, u64 b) {
    asm("fma.rn.f32x2 %0, %1, %2, %0;" : "+l"(d) : "l"(a), "l"(b));
}
__device__ __forceinline__ u64 mul2(u64 a, u64 b) {
    u64 d;
    asm("mul.rn.f32x2 %0, %1, %2;" : "=l"(d) : "l"(a), "l"(b));
    return d;
}

// ======================= mma.sync bf16 =====================================
__device__ __forceinline__ void mma16816(float* c, const unsigned* a, const unsigned* b) {
    asm volatile("mma.sync.aligned.m16n8k16.row.col.f32.bf16.bf16.f32 "
        "{%0,%1,%2,%3}, {%4,%5,%6,%7}, {%8,%9}, {%0,%1,%2,%3};"
        : "+f"(c[0]), "+f"(c[1]), "+f"(c[2]), "+f"(c[3])
        : "r"(a[0]), "r"(a[1]), "r"(a[2]), "r"(a[3]), "r"(b[0]), "r"(b[1]));
}
// split pair (x0,x1) -> whi = (bf16h(x0) | bf16h(x1)<<16), wlo = residuals
__device__ __forceinline__ void split2(float x0, float x1, unsigned& whi, unsigned& wlo) {
    __nv_bfloat16 h0 = __float2bfloat16(x0);
    __nv_bfloat16 h1 = __float2bfloat16(x1);
    __nv_bfloat16 l0 = __float2bfloat16(x0 - __bfloat162float(h0));
    __nv_bfloat16 l1 = __float2bfloat16(x1 - __bfloat162float(h1));
    whi = (unsigned)*(unsigned short*)&h0 | ((unsigned)*(unsigned short*)&h1 << 16);
    wlo = (unsigned)*(unsigned short*)&l0 | ((unsigned)*(unsigned short*)&l1 << 16);
}

// ======================= scratch =========================================
__device__ float g_k[B_*L_*D_];
__device__ float g_v[B_*L_*D_];
__device__ float g_q[B_*P_*L_*D_];
__device__ float g_ctx[B_*P_*L_*D_];
__device__ float g_W2q[DH_*D_];
__device__ float g_bq2[D_];

// ---------------------------------------------------------------------------
// Kernel 1: W2q = w2 @ wq, bq2 = b2 @ wq + bq
// ---------------------------------------------------------------------------
__global__ void fuse_w_kernel(const float* __restrict__ w2, const float* __restrict__ wq,
                              const float* __restrict__ b2, const float* __restrict__ bq) {
    int j = blockIdx.x, c = threadIdx.x;
    float acc = 0.f;
    for (int k = 0; k < D_; k++) acc = fmaf(w2[j*D_+k], wq[k*D_+c], acc);
    g_W2q[j*D_+c] = acc;
    if (j == 0) {
        float a = 0.f;
        for (int k = 0; k < D_; k++) a = fmaf(b2[k], wq[k*D_+c], a);
        g_bq2[c] = a + bq[c];
    }
}

// ---------------------------------------------------------------------------
// Kernel 2: k/v projections
// ---------------------------------------------------------------------------
__global__ void kv_kernel(const float* __restrict__ ehr,
                          const float* __restrict__ wk, const float* __restrict__ bk,
                          const float* __restrict__ wv, const float* __restrict__ bv) {
    __shared__ float sx[8*D_];
    int row0 = blockIdx.x * 8;
    int tid = threadIdx.x;
    for (int i = tid; i < 8*D_; i += 256) sx[i] = ehr[row0*D_ + i];
    __syncthreads();
    int c = tid;
    float ak[8], av[8];
    float bkc = bk[c], bvc = bv[c];
#pragma unroll
    for (int r = 0; r < 8; r++) { ak[r] = bkc; av[r] = bvc; }
    for (int d = 0; d < D_; d++) {
        float wkd = wk[d*D_+c];
        float wvd = wv[d*D_+c];
#pragma unroll
        for (int r = 0; r < 8; r++) {
            float x = sx[r*D_+d];
            ak[r] = fmaf(x, wkd, ak[r]);
            av[r] = fmaf(x, wvd, av[r]);
        }
    }
#pragma unroll
    for (int r = 0; r < 8; r++) {
        g_k[(row0+r)*D_+c] = ak[r];
        g_v[(row0+r)*D_+c] = av[r];
    }
}

// ---------------------------------------------------------------------------
// Kernel 3: time MLP -> q
// ---------------------------------------------------------------------------
__global__ void q_kernel(const float* __restrict__ ehr_times, const float* __restrict__ itv,
                         const float* __restrict__ w1, const float* __restrict__ b1) {
    __shared__ float sh[32*DH_];
    __shared__ float3 stf[32];
    int tid = threadIdx.x;
    int g0 = blockIdx.x * 32;
    int b  = g0 / (P_*L_);
    int p  = (g0 / L_) % P_;
    int l0 = g0 % L_;
    if (tid < 32) {
        float t = ehr_times[b*L_ + l0 + tid];
        float s = itv[(b*P_+p)*2 + 0];
        float e = itv[(b*P_+p)*2 + 1];
        float ds = t - s, de = e - t;
        float x  = ds * de;
        float sg = 1.f / (1.f + expf(-x));
        stf[tid] = make_float3(ds, de, sg);
    }
    __syncthreads();
    for (int i = tid; i < 32*DH_; i += 256) {
        int r = i >> 7, j = i & 127;
        float3 tf = stf[r];
        float z = tf.x*w1[j] + tf.y*w1[DH_+j] + tf.z*w1[2*DH_+j] + b1[j];
        sh[i] = 0.5f * z * (1.f + erff(z * 0.70710678118654752f));
    }
    __syncthreads();
    int c4 = (tid & 63) * 4;
    int rg = (tid >> 6) * 8;
    u64 acc[8][2];
    {
        ulonglong2 bias = *(const ulonglong2*)&g_bq2[c4];
#pragma unroll
        for (int r = 0; r < 8; r++) { acc[r][0] = bias.x; acc[r][1] = bias.y; }
    }
    for (int j = 0; j < DH_; j++) {
        ulonglong2 w = *(const ulonglong2*)&g_W2q[j*D_ + c4];
#pragma unroll
        for (int r = 0; r < 8; r++) {
            float x = sh[(rg+r)*DH_ + j];
            u64 x2 = pk2(x, x);
            fma2(acc[r][0], x2, w.x);
            fma2(acc[r][1], x2, w.y);
        }
    }
    const float scale = 0.17677669529663687f;
    u64 s2 = pk2(scale, scale);
#pragma unroll
    for (int r = 0; r < 8; r++) {
        ulonglong2 o;
        o.x = mul2(acc[r][0], s2);
        o.y = mul2(acc[r][1], s2);
        *(ulonglong2*)&g_q[(g0+rg+r)*D_ + c4] = o;
    }
}

// ---------------------------------------------------------------------------
// Kernel 4: attention via mma.sync bf16 hi/lo split.
// CTA = 64 queries of one (b,p,h). 128 threads = 4 warps, warp = 1 m16-pair tile.
// grid (H, L/64, B*P).
// ---------------------------------------------------------------------------
// smem layout (bytes):
#define SKH   0                 // K hi: [256][40] bf16 = 20480
#define SKL   20480             // K lo
#define SVTH  40960             // V^T hi: [32][264] bf16 = 16896
#define SVTL  57856             // V^T lo
#define SS    74752             // S: [64][260] f32 = 66560 (reused as packed P)
#define SBIAS 141312            // 256 f32
#define SDEN  142336            // 64 f32
#define SM_TOT 142592

#define KPAD  40                // K row pitch in bf16
#define VPAD  264               // V^T row pitch in bf16
#define SPAD  260               // S row pitch in f32

__global__ void __launch_bounds__(128, 1)
attn_kernel(const float* __restrict__ ehr_times, const float* __restrict__ itv) {
    extern __shared__ char sm[];
    int tid = threadIdx.x;
    int wid = tid >> 5, lane = tid & 31;
    int g   = lane >> 2;            // fragment group row 0..7
    int kq  = (lane & 3) * 2;       // fragment col pair base
    int h  = blockIdx.x;
    int qt = blockIdx.y;
    int bp = blockIdx.z;
    int b = bp >> 5, p = bp & 31;

    // ---- cooperative loads: K (split hi/lo), V^T (split), bias ----
    for (int idx = tid; idx < 4096; idx += 128) {
        int r = idx >> 4, d2 = (idx & 15) * 2;
        float2 kv = *(const float2*)&g_k[(b*L_ + r)*D_ + h*HD_ + d2];
        unsigned whi, wlo; split2(kv.x, kv.y, whi, wlo);
        *(unsigned*)(sm + SKH + r*(KPAD*2) + d2*2) = whi;
        *(unsigned*)(sm + SKL + r*(KPAD*2) + d2*2) = wlo;
    }
    for (int idx = tid; idx < 4096; idx += 128) {
        int hd = idx >> 7, k2 = (idx & 127) * 2;
        float v0 = g_v[(b*L_ + k2    )*D_ + h*HD_ + hd];
        float v1 = g_v[(b*L_ + k2 + 1)*D_ + h*HD_ + hd];
        unsigned whi, wlo; split2(v0, v1, whi, wlo);
        *(unsigned*)(sm + SVTH + hd*(VPAD*2) + k2*2) = whi;
        *(unsigned*)(sm + SVTL + hd*(VPAD*2) + k2*2) = wlo;
    }
    {
        float s = itv[(b*P_+p)*2 + 0];
        float e = itv[(b*P_+p)*2 + 1];
        float ctr = 0.5f*(s+e);
        for (int j = tid; j < L_; j += 128) {
            float t = ehr_times[b*L_ + j];
            ((float*)(sm + SBIAS))[j] = (t >= s && t <= e) ? -fabsf(t - ctr) : -1e30f;
        }
    }

    // ---- Q fragments straight from gmem (warp's 16 rows) ----
    unsigned qah[2][4], qal[2][4];
    {
        int qrow = (b*P_+p)*L_ + qt*64 + wid*16;
#pragma unroll
        for (int kt = 0; kt < 2; kt++) {
            int cb = h*HD_ + kt*16 + kq;
            float2 x0 = *(const float2*)&g_q[(qrow+g  )*D_ + cb];
            float2 x1 = *(const float2*)&g_q[(qrow+g+8)*D_ + cb];
            float2 x2 = *(const float2*)&g_q[(qrow+g  )*D_ + cb + 8];
            float2 x3 = *(const float2*)&g_q[(qrow+g+8)*D_ + cb + 8];
            split2(x0.x, x0.y, qah[kt][0], qal[kt][0]);
            split2(x1.x, x1.y, qah[kt][1], qal[kt][1]);
            split2(x2.x, x2.y, qah[kt][2], qal[kt][2]);
            split2(x3.x, x3.y, qah[kt][3], qal[kt][3]);
        }
    }
    __syncthreads();

    // ---- S = Q K^T  (per warp: 1 m-tile x 32 n-tiles x 2 k-steps, 3 products) ----
    float* S = (float*)(sm + SS);
#pragma unroll 4
    for (int nt = 0; nt < 32; nt++) {
        float c[4] = {0.f, 0.f, 0.f, 0.f};
        int nrow = nt*8 + g;
        const char* kh = sm + SKH + nrow*(KPAD*2);
        const char* kl = sm + SKL + nrow*(KPAD*2);
#pragma unroll
        for (int kt = 0; kt < 2; kt++) {
            unsigned bh[2], bl[2];
            bh[0] = *(const unsigned*)(kh + (kt*16 + kq)*2);
            bh[1] = *(const unsigned*)(kh + (kt*16 + kq + 8)*2);
            bl[0] = *(const unsigned*)(kl + (kt*16 + kq)*2);
            bl[1] = *(const unsigned*)(kl + (kt*16 + kq + 8)*2);
            mma16816(c, qah[kt], bh);
            mma16816(c, qal[kt], bh);
            mma16816(c, qah[kt], bl);
        }
        float* s0 = S + (wid*16 + g    )*SPAD + nt*8 + kq;
        float* s1 = S + (wid*16 + g + 8)*SPAD + nt*8 + kq;
        s0[0] = c[0]; s0[1] = c[1];
        s1[0] = c[2]; s1[1] = c[3];
    }
    __syncthreads();

    // ---- softmax: thread pair (t, t^1) per row; P packed (hi|lo<<16) in place ----
    {
        int row = tid >> 1, half = tid & 1;
        float* Sr = S + row*SPAD + half*128;
        const float* bias = (const float*)(sm + SBIAS) + half*128;
        float m = -1e30f;
        for (int j = 0; j < 128; j++) m = fmaxf(m, Sr[j] + bias[j]);
        m = fmaxf(m, __shfl_xor_sync(0xffffffffu, m, 1));
        float den = 0.f;
        unsigned* Pw = (unsigned*)Sr;
        for (int j = 0; j < 128; j++) {
            float pj = __expf(Sr[j] + bias[j] - m);
            den += pj;
            __nv_bfloat16 hb = __float2bfloat16(pj);
            __nv_bfloat16 lb = __float2bfloat16(pj - __bfloat162float(hb));
            Pw[j] = (unsigned)*(unsigned short*)&hb | ((unsigned)*(unsigned short*)&lb << 16);
        }
        den += __shfl_xor_sync(0xffffffffu, den, 1);
        if (half == 0) ((float*)(sm + SDEN))[row] = den;
    }
    __syncthreads();

    // ---- O = P V  (per warp: 1 m-tile x 4 n-tiles x 16 k-steps, 3 products) ----
    float o[4][4] = {};
    const unsigned* Pb = (const unsigned*)S;
#pragma unroll 2
    for (int kt = 0; kt < 16; kt++) {
        unsigned ah[4], al[4];
        {
            const unsigned* pr  = Pb + (wid*16 + g    )*SPAD + kt*16 + kq;
            const unsigned* pr8 = Pb + (wid*16 + g + 8)*SPAD + kt*16 + kq;
            unsigned w0, w1;
            w0 = pr[0];  w1 = pr[1];  ah[0] = __byte_perm(w0, w1, 0x5410); al[0] = __byte_perm(w0, w1, 0x7632);
            w0 = pr8[0]; w1 = pr8[1]; ah[1] = __byte_perm(w0, w1, 0x5410); al[1] = __byte_perm(w0, w1, 0x7632);
            w0 = pr[8];  w1 = pr[9];  ah[2] = __byte_perm(w0, w1, 0x5410); al[2] = __byte_perm(w0, w1, 0x7632);
            w0 = pr8[8]; w1 = pr8[9]; ah[3] = __byte_perm(w0, w1, 0x5410); al[3] = __byte_perm(w0, w1, 0x7632);
        }
#pragma unroll
        for (int nt = 0; nt < 4; nt++) {
            const char* vh = sm + SVTH + (nt*8 + g)*(VPAD*2) + (kt*16 + kq)*2;
            const char* vl = sm + SVTL + (nt*8 + g)*(VPAD*2) + (kt*16 + kq)*2;
            unsigned bh[2], bl[2];
            bh[0] = *(const unsigned*)vh; bh[1] = *(const unsigned*)(vh + 16);
            bl[0] = *(const unsigned*)vl; bl[1] = *(const unsigned*)(vl + 16);
            mma16816(o[nt], ah, bh);
            mma16816(o[nt], al, bh);
            mma16816(o[nt], ah, bl);
        }
    }

    // ---- epilogue: scale by 1/den, write ctx ----
    {
        float inv0 = 1.f / ((const float*)(sm + SDEN))[wid*16 + g];
        float inv1 = 1.f / ((const float*)(sm + SDEN))[wid*16 + g + 8];
        int orow = (b*P_+p)*L_ + qt*64 + wid*16;
#pragma unroll
        for (int nt = 0; nt < 4; nt++) {
            float2 v0 = make_float2(o[nt][0]*inv0, o[nt][1]*inv0);
            float2 v1 = make_float2(o[nt][2]*inv1, o[nt][3]*inv1);
            *(float2*)&g_ctx[(orow+g  )*D_ + h*HD_ + nt*8 + kq] = v0;
            *(float2*)&g_ctx[(orow+g+8)*D_ + h*HD_ + nt*8 + kq] = v1;
        }
    }
}

// ---------------------------------------------------------------------------
// Kernel 5: out = ctx @ wo + bo
// ---------------------------------------------------------------------------
__global__ void out_kernel(const float* __restrict__ wo, const float* __restrict__ bo,
                           float* __restrict__ out) {
    __shared__ float sx[32*D_];
    int tid = threadIdx.x;
    int row0 = blockIdx.x * 32;
    for (int i = tid; i < 32*D_; i += 256) sx[i] = g_ctx[row0*D_ + i];
    __syncthreads();
    int c4 = (tid & 63) * 4;
    int rg = (tid >> 6) * 8;
    u64 acc[8][2];
    {
        ulonglong2 bias = *(const ulonglong2*)&bo[c4];
#pragma unroll
        for (int r = 0; r < 8; r++) { acc[r][0] = bias.x; acc[r][1] = bias.y; }
    }
    for (int k = 0; k < D_; k++) {
        ulonglong2 w = *(const ulonglong2*)&wo[k*D_ + c4];
#pragma unroll
        for (int r = 0; r < 8; r++) {
            float x = sx[(rg+r)*D_ + k];
            u64 x2 = pk2(x, x);
            fma2(acc[r][0], x2, w.x);
            fma2(acc[r][1], x2, w.y);
        }
    }
#pragma unroll
    for (int r = 0; r < 8; r++) {
        ulonglong2 o; o.x = acc[r][0]; o.y = acc[r][1];
        *(ulonglong2*)&out[(row0+rg+r)*D_ + c4] = o;
    }
}

// ---------------------------------------------------------------------------
extern "C" void kernel_launch(void* const* d_in, const int* in_sizes, int n_in,
                              void* d_out, int out_size) {
    const float* ehr       = (const float*)d_in[0];
    const float* ehr_times = (const float*)d_in[1];
    const float* itv       = (const float*)d_in[2];
    const float* w1        = (const float*)d_in[3];
    const float* b1        = (const float*)d_in[4];
    const float* w2        = (const float*)d_in[5];
    const float* b2        = (const float*)d_in[6];
    const float* wq        = (const float*)d_in[7];
    const float* bq        = (const float*)d_in[8];
    const float* wk        = (const float*)d_in[9];
    const float* bk        = (const float*)d_in[10];
    const float* wv        = (const float*)d_in[11];
    const float* bv        = (const float*)d_in[12];
    const float* wo        = (const float*)d_in[13];
    const float* bo        = (const float*)d_in[14];
    float* out = (float*)d_out;

    fuse_w_kernel<<<DH_, D_>>>(w2, wq, b2, bq);
    kv_kernel<<<B_*L_/8, 256>>>(ehr, wk, bk, wv, bv);
    q_kernel<<<B_*P_*L_/32, 256>>>(ehr_times, itv, w1, b1);

    cudaFuncSetAttribute(attn_kernel, cudaFuncAttributeMaxDynamicSharedMemorySize, SM_TOT);
    attn_kernel<<<dim3(H_, L_/64, B_*P_), 128, SM_TOT>>>(ehr_times, itv);

    out_kernel<<<B_*P_*L_/32, 256>>>(wo, bo, out);
}

// round 5
// speedup vs baseline: 2.1171x; 2.1171x over previous
#include <cuda_runtime.h>
#include <cuda_bf16.h>
#include <math.h>
#include <cstdint>

#define B_  4
#define L_  256
#define D_  256
#define P_  32
#define H_  8
#define HD_ 32
#define DH_ 128   // D/2

typedef unsigned long long u64;

// ======================= packed f32x2 helpers ==============================
__device__ __forceinline__ u64 pk2(float lo, float hi) {
    u64 r;
    asm("mov.b64 %0, {%1, %2};" : "=l"(r) : "r"(__float_as_uint(lo)), "r"(__float_as_uint(hi)));
    return r;
}
__device__ __forceinline__ void fma2(u64& d, u64 a, u64 b) {
    asm("fma.rn.f32x2 %0, %1, %2, %0;" : "+l"(d) : "l"(a), "l"(b));
}
__device__ __forceinline__ u64 mul2(u64 a, u64 b) {
    u64 d;
    asm("mul.rn.f32x2 %0, %1, %2;" : "=l"(d) : "l"(a), "l"(b));
    return d;
}

// ======================= mma.sync bf16 =====================================
__device__ __forceinline__ void mma16816(float* c, const unsigned* a, const unsigned* b) {
    asm volatile("mma.sync.aligned.m16n8k16.row.col.f32.bf16.bf16.f32 "
        "{%0,%1,%2,%3}, {%4,%5,%6,%7}, {%8,%9}, {%0,%1,%2,%3};"
        : "+f"(c[0]), "+f"(c[1]), "+f"(c[2]), "+f"(c[3])
        : "r"(a[0]), "r"(a[1]), "r"(a[2]), "r"(a[3]), "r"(b[0]), "r"(b[1]));
}
__device__ __forceinline__ void split2(float x0, float x1, unsigned& whi, unsigned& wlo) {
    __nv_bfloat16 h0 = __float2bfloat16(x0);
    __nv_bfloat16 h1 = __float2bfloat16(x1);
    __nv_bfloat16 l0 = __float2bfloat16(x0 - __bfloat162float(h0));
    __nv_bfloat16 l1 = __float2bfloat16(x1 - __bfloat162float(h1));
    whi = (unsigned)*(unsigned short*)&h0 | ((unsigned)*(unsigned short*)&h1 << 16);
    wlo = (unsigned)*(unsigned short*)&l0 | ((unsigned)*(unsigned short*)&l1 << 16);
}

// ======================= scratch =========================================
__device__ __nv_bfloat16 g_kh[B_*L_*D_];
__device__ __nv_bfloat16 g_kl[B_*L_*D_];
__device__ __nv_bfloat16 g_vth[B_*D_*L_];   // [(b*D + c)][l]
__device__ __nv_bfloat16 g_vtl[B_*D_*L_];
__device__ __nv_bfloat16 g_qh[B_*P_*L_*D_];
__device__ __nv_bfloat16 g_ql[B_*P_*L_*D_];
__device__ float g_ctx[B_*P_*L_*D_];
__device__ float g_W2q[DH_*D_];
__device__ float g_bq2[D_];

// ---------------------------------------------------------------------------
// Kernel 1: W2q = w2 @ wq, bq2 = b2 @ wq + bq
// ---------------------------------------------------------------------------
__global__ void fuse_w_kernel(const float* __restrict__ w2, const float* __restrict__ wq,
                              const float* __restrict__ b2, const float* __restrict__ bq) {
    int j = blockIdx.x, c = threadIdx.x;
    float acc = 0.f;
    for (int k = 0; k < D_; k++) acc = fmaf(w2[j*D_+k], wq[k*D_+c], acc);
    g_W2q[j*D_+c] = acc;
    if (j == 0) {
        float a = 0.f;
        for (int k = 0; k < D_; k++) a = fmaf(b2[k], wq[k*D_+c], a);
        g_bq2[c] = a + bq[c];
    }
}

// ---------------------------------------------------------------------------
// Kernel 2: k/v projections, emitted as bf16 hi/lo (K row-major, V transposed)
// ---------------------------------------------------------------------------
__global__ void kv_kernel(const float* __restrict__ ehr,
                          const float* __restrict__ wk, const float* __restrict__ bk,
                          const float* __restrict__ wv, const float* __restrict__ bv) {
    __shared__ float sx[8*D_];
    int row0 = blockIdx.x * 8;
    int tid = threadIdx.x;
    for (int i = tid; i < 8*D_; i += 256) sx[i] = ehr[row0*D_ + i];
    __syncthreads();
    int c = tid;
    float ak[8], av[8];
    float bkc = bk[c], bvc = bv[c];
#pragma unroll
    for (int r = 0; r < 8; r++) { ak[r] = bkc; av[r] = bvc; }
    for (int d = 0; d < D_; d++) {
        float wkd = wk[d*D_+c];
        float wvd = wv[d*D_+c];
#pragma unroll
        for (int r = 0; r < 8; r++) {
            float x = sx[r*D_+d];
            ak[r] = fmaf(x, wkd, ak[r]);
            av[r] = fmaf(x, wvd, av[r]);
        }
    }
    // K: split, coalesced 2B stores
#pragma unroll
    for (int r = 0; r < 8; r++) {
        __nv_bfloat16 h = __float2bfloat16(ak[r]);
        __nv_bfloat16 l = __float2bfloat16(ak[r] - __bfloat162float(h));
        g_kh[(row0+r)*D_+c] = h;
        g_kl[(row0+r)*D_+c] = l;
    }
    // V^T: thread holds 8 consecutive l-values for column c -> 16B vector stores
    {
        int b  = row0 / L_;
        int l0 = row0 % L_;
        __nv_bfloat16 vh8[8], vl8[8];
#pragma unroll
        for (int r = 0; r < 8; r++) {
            __nv_bfloat16 h = __float2bfloat16(av[r]);
            vh8[r] = h;
            vl8[r] = __float2bfloat16(av[r] - __bfloat162float(h));
        }
        *(uint4*)&g_vth[(b*D_ + c)*L_ + l0] = *(uint4*)vh8;
        *(uint4*)&g_vtl[(b*D_ + c)*L_ + l0] = *(uint4*)vl8;
    }
}

// ---------------------------------------------------------------------------
// Kernel 3: time MLP -> q (bf16 hi/lo output)
// ---------------------------------------------------------------------------
__global__ void q_kernel(const float* __restrict__ ehr_times, const float* __restrict__ itv,
                         const float* __restrict__ w1, const float* __restrict__ b1) {
    __shared__ float sh[32*DH_];
    __shared__ float3 stf[32];
    int tid = threadIdx.x;
    int g0 = blockIdx.x * 32;
    int b  = g0 / (P_*L_);
    int p  = (g0 / L_) % P_;
    int l0 = g0 % L_;
    if (tid < 32) {
        float t = ehr_times[b*L_ + l0 + tid];
        float s = itv[(b*P_+p)*2 + 0];
        float e = itv[(b*P_+p)*2 + 1];
        float ds = t - s, de = e - t;
        float x  = ds * de;
        float sg = 1.f / (1.f + expf(-x));
        stf[tid] = make_float3(ds, de, sg);
    }
    __syncthreads();
    for (int i = tid; i < 32*DH_; i += 256) {
        int r = i >> 7, j = i & 127;
        float3 tf = stf[r];
        float z = tf.x*w1[j] + tf.y*w1[DH_+j] + tf.z*w1[2*DH_+j] + b1[j];
        sh[i] = 0.5f * z * (1.f + erff(z * 0.70710678118654752f));
    }
    __syncthreads();
    int c4 = (tid & 63) * 4;
    int rg = (tid >> 6) * 8;
    u64 acc[8][2];
    {
        ulonglong2 bias = *(const ulonglong2*)&g_bq2[c4];
#pragma unroll
        for (int r = 0; r < 8; r++) { acc[r][0] = bias.x; acc[r][1] = bias.y; }
    }
    for (int j = 0; j < DH_; j++) {
        ulonglong2 w = *(const ulonglong2*)&g_W2q[j*D_ + c4];
#pragma unroll
        for (int r = 0; r < 8; r++) {
            float x = sh[(rg+r)*DH_ + j];
            u64 x2 = pk2(x, x);
            fma2(acc[r][0], x2, w.x);
            fma2(acc[r][1], x2, w.y);
        }
    }
    const float scale = 0.17677669529663687f;
#pragma unroll
    for (int r = 0; r < 8; r++) {
        float2 lohalf, hihalf;
        {
            u64 s2 = pk2(scale, scale);
            u64 a0 = mul2(acc[r][0], s2);
            u64 a1 = mul2(acc[r][1], s2);
            lohalf = *(float2*)&a0;
            hihalf = *(float2*)&a1;
        }
        unsigned h0, l0w, h1, l1w;
        split2(lohalf.x, lohalf.y, h0, l0w);
        split2(hihalf.x, hihalf.y, h1, l1w);
        uint2 hv; hv.x = h0; hv.y = h1;
        uint2 lv; lv.x = l0w; lv.y = l1w;
        *(uint2*)&g_qh[(size_t)(g0+rg+r)*D_ + c4] = hv;
        *(uint2*)&g_ql[(size_t)(g0+rg+r)*D_ + c4] = lv;
    }
}

// ---------------------------------------------------------------------------
// Kernel 4: fragment-resident flash attention (mma.sync bf16 hi/lo).
// CTA = 128 queries of one (b,p,h). 256 thr = 8 warps, warp = 16 queries.
// grid (H, 2, B*P). S stays in registers: c[32][4].
// ---------------------------------------------------------------------------
#define AKH 0                 // K hi [256][40] bf16 = 20480
#define AKL 20480
#define AVH 40960             // V^T hi [32][264] bf16 = 16896
#define AVL 57856
#define ABI 74752             // 256 f32 bias
#define ASM_TOT 75776
#define KP  40                // K row pitch (bf16)
#define VP  264               // V^T row pitch (bf16)

__global__ void __launch_bounds__(256, 1)
attn_kernel(const float* __restrict__ ehr_times, const float* __restrict__ itv) {
    extern __shared__ char sm[];
    int tid = threadIdx.x;
    int wid = tid >> 5, lane = tid & 31;
    int g  = lane >> 2;
    int kq = (lane & 3) * 2;
    int h    = blockIdx.x;
    int half = blockIdx.y;
    int bp   = blockIdx.z;          // = b*P + p
    int b = bp >> 5, p = bp & 31;

    // ---- fill K tiles (plain copies, pre-split upstream) ----
    {
        const __nv_bfloat16* kh = g_kh + (size_t)(b*L_)*D_ + h*HD_;
        const __nv_bfloat16* kl = g_kl + (size_t)(b*L_)*D_ + h*HD_;
        for (int idx = tid; idx < 2048; idx += 256) {
            int r = idx >> 3, c4 = (idx & 7) * 4;
            *(uint2*)(sm + AKH + r*(KP*2) + c4*2) = *(const uint2*)(kh + r*D_ + c4);
            *(uint2*)(sm + AKL + r*(KP*2) + c4*2) = *(const uint2*)(kl + r*D_ + c4);
        }
    }
    // ---- fill V^T tiles ----
    {
        const __nv_bfloat16* vh = g_vth + (size_t)(b*D_ + h*HD_)*L_;
        const __nv_bfloat16* vl = g_vtl + (size_t)(b*D_ + h*HD_)*L_;
        for (int idx = tid; idx < 1024; idx += 256) {
            int hd = idx >> 5, c8 = (idx & 31) * 8;
            *(uint4*)(sm + AVH + hd*(VP*2) + c8*2) = *(const uint4*)(vh + hd*L_ + c8);
            *(uint4*)(sm + AVL + hd*(VP*2) + c8*2) = *(const uint4*)(vl + hd*L_ + c8);
        }
    }
    // ---- bias ----
    {
        float s = itv[bp*2 + 0];
        float e = itv[bp*2 + 1];
        float ctr = 0.5f*(s+e);
        if (tid < 256) {
            float t = ehr_times[b*L_ + tid];
            ((float*)(sm + ABI))[tid] = (t >= s && t <= e) ? -fabsf(t - ctr) : -1e30f;
        }
    }

    // ---- Q fragments from gmem (pre-split) ----
    unsigned qah[2][4], qal[2][4];
    {
        size_t qrow = (size_t)bp*L_ + half*128 + wid*16;
#pragma unroll
        for (int kt = 0; kt < 2; kt++) {
            size_t base = (qrow + g)*D_ + h*HD_ + kt*16 + kq;
            qah[kt][0] = *(const unsigned*)(g_qh + base);
            qah[kt][1] = *(const unsigned*)(g_qh + base + 8*D_);
            qah[kt][2] = *(const unsigned*)(g_qh + base + 8);
            qah[kt][3] = *(const unsigned*)(g_qh + base + 8*D_ + 8);
            qal[kt][0] = *(const unsigned*)(g_ql + base);
            qal[kt][1] = *(const unsigned*)(g_ql + base + 8*D_);
            qal[kt][2] = *(const unsigned*)(g_ql + base + 8);
            qal[kt][3] = *(const unsigned*)(g_ql + base + 8*D_ + 8);
        }
    }
    __syncthreads();

    // ---- S = Q K^T, fragments resident: c[nt][0..1]=row g, [2..3]=row g+8 ----
    float c[32][4];
#pragma unroll
    for (int nt = 0; nt < 32; nt++) { c[nt][0]=0.f; c[nt][1]=0.f; c[nt][2]=0.f; c[nt][3]=0.f; }
#pragma unroll
    for (int nt = 0; nt < 32; nt++) {
        const char* kb = sm + (nt*8 + g)*(KP*2);
#pragma unroll
        for (int kt = 0; kt < 2; kt++) {
            unsigned bh[2], bl[2];
            bh[0] = *(const unsigned*)(kb + AKH + (kt*16 + kq)*2);
            bh[1] = *(const unsigned*)(kb + AKH + (kt*16 + kq)*2 + 16);
            bl[0] = *(const unsigned*)(kb + AKL + (kt*16 + kq)*2);
            bl[1] = *(const unsigned*)(kb + AKL + (kt*16 + kq)*2 + 16);
            mma16816(c[nt], qah[kt], bh);
            mma16816(c[nt], qal[kt], bh);
            mma16816(c[nt], qah[kt], bl);
        }
    }

    // ---- softmax in registers (rows g and g+8), quad shfl reductions ----
    const float* sb = (const float*)(sm + ABI);
    float m0 = -1e30f, m1 = -1e30f;
#pragma unroll
    for (int nt = 0; nt < 32; nt++) {
        float2 bb = *(const float2*)&sb[nt*8 + kq];
        m0 = fmaxf(m0, fmaxf(c[nt][0] + bb.x, c[nt][1] + bb.y));
        m1 = fmaxf(m1, fmaxf(c[nt][2] + bb.x, c[nt][3] + bb.y));
    }
    m0 = fmaxf(m0, __shfl_xor_sync(0xffffffffu, m0, 1));
    m0 = fmaxf(m0, __shfl_xor_sync(0xffffffffu, m0, 2));
    m1 = fmaxf(m1, __shfl_xor_sync(0xffffffffu, m1, 1));
    m1 = fmaxf(m1, __shfl_xor_sync(0xffffffffu, m1, 2));
    float d0 = 0.f, d1 = 0.f;
#pragma unroll
    for (int nt = 0; nt < 32; nt++) {
        float2 bb = *(const float2*)&sb[nt*8 + kq];
        c[nt][0] = __expf(c[nt][0] + bb.x - m0);
        c[nt][1] = __expf(c[nt][1] + bb.y - m0);
        c[nt][2] = __expf(c[nt][2] + bb.x - m1);
        c[nt][3] = __expf(c[nt][3] + bb.y - m1);
        d0 += c[nt][0] + c[nt][1];
        d1 += c[nt][2] + c[nt][3];
    }
    d0 += __shfl_xor_sync(0xffffffffu, d0, 1);
    d0 += __shfl_xor_sync(0xffffffffu, d0, 2);
    d1 += __shfl_xor_sync(0xffffffffu, d1, 1);
    d1 += __shfl_xor_sync(0xffffffffu, d1, 2);

    // ---- O = P V: P fragments come straight from c[][] ----
    float o[4][4];
#pragma unroll
    for (int nt = 0; nt < 4; nt++) { o[nt][0]=0.f; o[nt][1]=0.f; o[nt][2]=0.f; o[nt][3]=0.f; }
#pragma unroll
    for (int kt = 0; kt < 16; kt++) {
        unsigned ah[4], al[4];
        split2(c[2*kt][0],   c[2*kt][1],   ah[0], al[0]);
        split2(c[2*kt][2],   c[2*kt][3],   ah[1], al[1]);
        split2(c[2*kt+1][0], c[2*kt+1][1], ah[2], al[2]);
        split2(c[2*kt+1][2], c[2*kt+1][3], ah[3], al[3]);
#pragma unroll
        for (int nt = 0; nt < 4; nt++) {
            const char* vb = sm + (nt*8 + g)*(VP*2) + (kt*16 + kq)*2;
            unsigned bh[2], bl[2];
            bh[0] = *(const unsigned*)(vb + AVH);
            bh[1] = *(const unsigned*)(vb + AVH + 16);
            bl[0] = *(const unsigned*)(vb + AVL);
            bl[1] = *(const unsigned*)(vb + AVL + 16);
            mma16816(o[nt], ah, bh);
            mma16816(o[nt], al, bh);
            mma16816(o[nt], ah, bl);
        }
    }

    // ---- epilogue ----
    {
        float inv0 = 1.f / d0, inv1 = 1.f / d1;
        size_t orow = (size_t)bp*L_ + half*128 + wid*16;
#pragma unroll
        for (int nt = 0; nt < 4; nt++) {
            float2 v0 = make_float2(o[nt][0]*inv0, o[nt][1]*inv0);
            float2 v1 = make_float2(o[nt][2]*inv1, o[nt][3]*inv1);
            *(float2*)&g_ctx[(orow+g  )*D_ + h*HD_ + nt*8 + kq] = v0;
            *(float2*)&g_ctx[(orow+g+8)*D_ + h*HD_ + nt*8 + kq] = v1;
        }
    }
}

// ---------------------------------------------------------------------------
// Kernel 5: out = ctx @ wo + bo  (scalar f32x2)
// ---------------------------------------------------------------------------
__global__ void out_kernel(const float* __restrict__ wo, const float* __restrict__ bo,
                           float* __restrict__ out) {
    __shared__ float sx[32*D_];
    int tid = threadIdx.x;
    int row0 = blockIdx.x * 32;
    for (int i = tid; i < 32*D_; i += 256) sx[i] = g_ctx[row0*D_ + i];
    __syncthreads();
    int c4 = (tid & 63) * 4;
    int rg = (tid >> 6) * 8;
    u64 acc[8][2];
    {
        ulonglong2 bias = *(const ulonglong2*)&bo[c4];
#pragma unroll
        for (int r = 0; r < 8; r++) { acc[r][0] = bias.x; acc[r][1] = bias.y; }
    }
    for (int k = 0; k < D_; k++) {
        ulonglong2 w = *(const ulonglong2*)&wo[k*D_ + c4];
#pragma unroll
        for (int r = 0; r < 8; r++) {
            float x = sx[(rg+r)*D_ + k];
            u64 x2 = pk2(x, x);
            fma2(acc[r][0], x2, w.x);
            fma2(acc[r][1], x2, w.y);
        }
    }
#pragma unroll
    for (int r = 0; r < 8; r++) {
        ulonglong2 o; o.x = acc[r][0]; o.y = acc[r][1];
        *(ulonglong2*)&out[(row0+rg+r)*D_ + c4] = o;
    }
}

// ---------------------------------------------------------------------------
extern "C" void kernel_launch(void* const* d_in, const int* in_sizes, int n_in,
                              void* d_out, int out_size) {
    const float* ehr       = (const float*)d_in[0];
    const float* ehr_times = (const float*)d_in[1];
    const float* itv       = (const float*)d_in[2];
    const float* w1        = (const float*)d_in[3];
    const float* b1        = (const float*)d_in[4];
    const float* w2        = (const float*)d_in[5];
    const float* b2        = (const float*)d_in[6];
    const float* wq        = (const float*)d_in[7];
    const float* bq        = (const float*)d_in[8];
    const float* wk        = (const float*)d_in[9];
    const float* bk        = (const float*)d_in[10];
    const float* wv        = (const float*)d_in[11];
    const float* bv        = (const float*)d_in[12];
    const float* wo        = (const float*)d_in[13];
    const float* bo        = (const float*)d_in[14];
    float* out = (float*)d_out;

    fuse_w_kernel<<<DH_, D_>>>(w2, wq, b2, bq);
    kv_kernel<<<B_*L_/8, 256>>>(ehr, wk, bk, wv, bv);
    q_kernel<<<B_*P_*L_/32, 256>>>(ehr_times, itv, w1, b1);

    cudaFuncSetAttribute(attn_kernel, cudaFuncAttributeMaxDynamicSharedMemorySize, ASM_TOT);
    attn_kernel<<<dim3(H_, 2, B_*P_), 256, ASM_TOT>>>(ehr_times, itv);

    out_kernel<<<B_*P_*L_/32, 256>>>(wo, bo, out);
}

// round 6
// speedup vs baseline: 2.9206x; 1.3796x over previous
#include <cuda_runtime.h>
#include <cuda_bf16.h>
#include <math.h>
#include <cstdint>

#define B_  4
#define L_  256
#define D_  256
#define P_  32
#define H_  8
#define HD_ 32
#define DH_ 128   // D/2

typedef unsigned long long u64;

// ======================= packed f32x2 helpers ==============================
__device__ __forceinline__ u64 pk2(float lo, float hi) {
    u64 r;
    asm("mov.b64 %0, {%1, %2};" : "=l"(r) : "r"(__float_as_uint(lo)), "r"(__float_as_uint(hi)));
    return r;
}
__device__ __forceinline__ void fma2(u64& d, u64 a, u64 b) {
    asm("fma.rn.f32x2 %0, %1, %2, %0;" : "+l"(d) : "l"(a), "l"(b));
}

// ======================= mma.sync bf16 =====================================
__device__ __forceinline__ void mma16816(float* c, const unsigned* a, const unsigned* b) {
    asm volatile("mma.sync.aligned.m16n8k16.row.col.f32.bf16.bf16.f32 "
        "{%0,%1,%2,%3}, {%4,%5,%6,%7}, {%8,%9}, {%0,%1,%2,%3};"
        : "+f"(c[0]), "+f"(c[1]), "+f"(c[2]), "+f"(c[3])
        : "r"(a[0]), "r"(a[1]), "r"(a[2]), "r"(a[3]), "r"(b[0]), "r"(b[1]));
}
__device__ __forceinline__ void split2(float x0, float x1, unsigned& whi, unsigned& wlo) {
    __nv_bfloat16 h0 = __float2bfloat16(x0);
    __nv_bfloat16 h1 = __float2bfloat16(x1);
    __nv_bfloat16 l0 = __float2bfloat16(x0 - __bfloat162float(h0));
    __nv_bfloat16 l1 = __float2bfloat16(x1 - __bfloat162float(h1));
    whi = (unsigned)*(unsigned short*)&h0 | ((unsigned)*(unsigned short*)&h1 << 16);
    wlo = (unsigned)*(unsigned short*)&l0 | ((unsigned)*(unsigned short*)&l1 << 16);
}
__device__ __forceinline__ void split1(float x, __nv_bfloat16& h, __nv_bfloat16& l) {
    h = __float2bfloat16(x);
    l = __float2bfloat16(x - __bfloat162float(h));
}

// ======================= scratch =========================================
__device__ __nv_bfloat16 g_kh[B_*L_*D_];
__device__ __nv_bfloat16 g_kl[B_*L_*D_];
__device__ __nv_bfloat16 g_vth[B_*D_*L_];       // [(b*D + c)][l]
__device__ __nv_bfloat16 g_vtl[B_*D_*L_];
__device__ __nv_bfloat16 g_qh[B_*P_*L_*D_];
__device__ __nv_bfloat16 g_ql[B_*P_*L_*D_];
__device__ __nv_bfloat16 g_ctxh[B_*P_*L_*D_];
__device__ __nv_bfloat16 g_ctxl[B_*P_*L_*D_];
__device__ __nv_bfloat16 g_hh[B_*P_*L_*DH_];
__device__ __nv_bfloat16 g_hl[B_*P_*L_*DH_];
__device__ __nv_bfloat16 g_woTh[D_*D_];         // [n][k]
__device__ __nv_bfloat16 g_woTl[D_*D_];
__device__ __nv_bfloat16 g_w2qTh[D_*DH_];       // [n][k], scale folded
__device__ __nv_bfloat16 g_w2qTl[D_*DH_];
__device__ float g_W2q[DH_*D_];
__device__ float g_bq2[D_];                     // scale folded

// ---------------------------------------------------------------------------
// Kernel 1: W2q = w2 @ wq, bq2 = scale*(b2 @ wq + bq)
// ---------------------------------------------------------------------------
__global__ void fuse_w_kernel(const float* __restrict__ w2, const float* __restrict__ wq,
                              const float* __restrict__ b2, const float* __restrict__ bq) {
    int j = blockIdx.x, c = threadIdx.x;
    float acc = 0.f;
    for (int k = 0; k < D_; k++) acc = fmaf(w2[j*D_+k], wq[k*D_+c], acc);
    g_W2q[j*D_+c] = acc;
    if (j == 0) {
        float a = 0.f;
        for (int k = 0; k < D_; k++) a = fmaf(b2[k], wq[k*D_+c], a);
        g_bq2[c] = 0.17677669529663687f * (a + bq[c]);
    }
}

// ---------------------------------------------------------------------------
// Kernel 1b: transpose+split wo and scale*W2q  (grid 256 = n, block 256 = k)
// ---------------------------------------------------------------------------
__global__ void prep_split_kernel(const float* __restrict__ wo) {
    int n = blockIdx.x, k = threadIdx.x;
    __nv_bfloat16 h, l;
    split1(wo[k*D_ + n], h, l);
    g_woTh[n*D_ + k] = h;
    g_woTl[n*D_ + k] = l;
    if (k < DH_) {
        split1(0.17677669529663687f * g_W2q[k*D_ + n], h, l);
        g_w2qTh[n*DH_ + k] = h;
        g_w2qTl[n*DH_ + k] = l;
    }
}

// ---------------------------------------------------------------------------
// Kernel 2: k/v projections, emitted as bf16 hi/lo (K row-major, V transposed)
// ---------------------------------------------------------------------------
__global__ void kv_kernel(const float* __restrict__ ehr,
                          const float* __restrict__ wk, const float* __restrict__ bk,
                          const float* __restrict__ wv, const float* __restrict__ bv) {
    __shared__ float sx[8*D_];
    int row0 = blockIdx.x * 8;
    int tid = threadIdx.x;
    for (int i = tid; i < 8*D_; i += 256) sx[i] = ehr[row0*D_ + i];
    __syncthreads();
    int c = tid;
    float ak[8], av[8];
    float bkc = bk[c], bvc = bv[c];
#pragma unroll
    for (int r = 0; r < 8; r++) { ak[r] = bkc; av[r] = bvc; }
    for (int d = 0; d < D_; d++) {
        float wkd = wk[d*D_+c];
        float wvd = wv[d*D_+c];
#pragma unroll
        for (int r = 0; r < 8; r++) {
            float x = sx[r*D_+d];
            ak[r] = fmaf(x, wkd, ak[r]);
            av[r] = fmaf(x, wvd, av[r]);
        }
    }
#pragma unroll
    for (int r = 0; r < 8; r++) {
        __nv_bfloat16 h, l;
        split1(ak[r], h, l);
        g_kh[(row0+r)*D_+c] = h;
        g_kl[(row0+r)*D_+c] = l;
    }
    {
        int b  = row0 / L_;
        int l0 = row0 % L_;
        __nv_bfloat16 vh8[8], vl8[8];
#pragma unroll
        for (int r = 0; r < 8; r++) split1(av[r], vh8[r], vl8[r]);
        *(uint4*)&g_vth[(b*D_ + c)*L_ + l0] = *(uint4*)vh8;
        *(uint4*)&g_vtl[(b*D_ + c)*L_ + l0] = *(uint4*)vl8;
    }
}

// ---------------------------------------------------------------------------
// Kernel 3: time features -> MLP -> gelu -> h (split bf16)
// grid 1024 (32 rows/block), block 256
// ---------------------------------------------------------------------------
__global__ void h_kernel(const float* __restrict__ ehr_times, const float* __restrict__ itv,
                         const float* __restrict__ w1, const float* __restrict__ b1) {
    __shared__ float3 stf[32];
    int tid = threadIdx.x;
    int g0 = blockIdx.x * 32;
    int b  = g0 / (P_*L_);
    int p  = (g0 / L_) % P_;
    int l0 = g0 % L_;
    if (tid < 32) {
        float t = ehr_times[b*L_ + l0 + tid];
        float s = itv[(b*P_+p)*2 + 0];
        float e = itv[(b*P_+p)*2 + 1];
        float ds = t - s, de = e - t;
        float x  = ds * de;
        float sg = 1.f / (1.f + expf(-x));
        stf[tid] = make_float3(ds, de, sg);
    }
    __syncthreads();
    for (int i = tid; i < 32*DH_; i += 256) {
        int r = i >> 7, j = i & 127;
        float3 tf = stf[r];
        float z = tf.x*w1[j] + tf.y*w1[DH_+j] + tf.z*w1[2*DH_+j] + b1[j];
        float v = 0.5f * z * (1.f + erff(z * 0.70710678118654752f));
        __nv_bfloat16 h, l;
        split1(v, h, l);
        g_hh[(size_t)g0*DH_ + i] = h;
        g_hl[(size_t)g0*DH_ + i] = l;
    }
}

// ---------------------------------------------------------------------------
// Generic bf16 hi/lo 3-product GEMM:  C[M x 256] = A[M x K] @ BT[256 x K]^T + bias
// CTA = 128m x 128n, 256 thr, 8 warps (4m x 2n), warp = 32m x 64n.
// SPLIT: epilogue writes bf16 hi/lo (for q); else fp32.
// ---------------------------------------------------------------------------
template<int K, bool SPLIT>
__global__ void __launch_bounds__(256)
gemm_kernel(const __nv_bfloat16* __restrict__ Ah, const __nv_bfloat16* __restrict__ Al,
            const __nv_bfloat16* __restrict__ BTh, const __nv_bfloat16* __restrict__ BTl,
            const float* __restrict__ bias,
            float* __restrict__ outF,
            __nv_bfloat16* __restrict__ outH, __nv_bfloat16* __restrict__ outL) {
    __shared__ __nv_bfloat16 sAh[128*40], sAl[128*40], sBh[128*40], sBl[128*40];
    int tid = threadIdx.x, wid = tid >> 5, lane = tid & 31;
    int g = lane >> 2, kq = (lane & 3) * 2;
    int wm = wid & 3, wn = wid >> 2;
    int m0 = blockIdx.x * 128, n0 = blockIdx.y * 128;

    float c[2][8][4];
#pragma unroll
    for (int nt = 0; nt < 8; nt++) {
        float2 bb = *(const float2*)&bias[n0 + wn*64 + nt*8 + kq];
#pragma unroll
        for (int mt = 0; mt < 2; mt++) {
            c[mt][nt][0] = bb.x; c[mt][nt][1] = bb.y;
            c[mt][nt][2] = bb.x; c[mt][nt][3] = bb.y;
        }
    }

    for (int kc = 0; kc < K; kc += 32) {
        for (int idx = tid; idx < 1024; idx += 256) {
            int r = idx >> 3, c4 = (idx & 7) * 4;
            *(uint2*)&sAh[r*40 + c4] = *(const uint2*)&Ah[(size_t)(m0+r)*K + kc + c4];
            *(uint2*)&sAl[r*40 + c4] = *(const uint2*)&Al[(size_t)(m0+r)*K + kc + c4];
            *(uint2*)&sBh[r*40 + c4] = *(const uint2*)&BTh[(size_t)(n0+r)*K + kc + c4];
            *(uint2*)&sBl[r*40 + c4] = *(const uint2*)&BTl[(size_t)(n0+r)*K + kc + c4];
        }
        __syncthreads();
#pragma unroll
        for (int kt = 0; kt < 2; kt++) {
            unsigned ah[2][4], al[2][4];
#pragma unroll
            for (int mt = 0; mt < 2; mt++) {
                int rb = wm*32 + mt*16;
                ah[mt][0] = *(const unsigned*)&sAh[(rb+g  )*40 + kt*16 + kq];
                ah[mt][1] = *(const unsigned*)&sAh[(rb+g+8)*40 + kt*16 + kq];
                ah[mt][2] = *(const unsigned*)&sAh[(rb+g  )*40 + kt*16 + kq + 8];
                ah[mt][3] = *(const unsigned*)&sAh[(rb+g+8)*40 + kt*16 + kq + 8];
                al[mt][0] = *(const unsigned*)&sAl[(rb+g  )*40 + kt*16 + kq];
                al[mt][1] = *(const unsigned*)&sAl[(rb+g+8)*40 + kt*16 + kq];
                al[mt][2] = *(const unsigned*)&sAl[(rb+g  )*40 + kt*16 + kq + 8];
                al[mt][3] = *(const unsigned*)&sAl[(rb+g+8)*40 + kt*16 + kq + 8];
            }
#pragma unroll
            for (int nt = 0; nt < 8; nt++) {
                int rn = wn*64 + nt*8 + g;
                unsigned bh[2], bl[2];
                bh[0] = *(const unsigned*)&sBh[rn*40 + kt*16 + kq];
                bh[1] = *(const unsigned*)&sBh[rn*40 + kt*16 + kq + 8];
                bl[0] = *(const unsigned*)&sBl[rn*40 + kt*16 + kq];
                bl[1] = *(const unsigned*)&sBl[rn*40 + kt*16 + kq + 8];
#pragma unroll
                for (int mt = 0; mt < 2; mt++) {
                    mma16816(c[mt][nt], ah[mt], bh);
                    mma16816(c[mt][nt], al[mt], bh);
                    mma16816(c[mt][nt], ah[mt], bl);
                }
            }
        }
        __syncthreads();
    }

#pragma unroll
    for (int mt = 0; mt < 2; mt++) {
        int r0 = m0 + wm*32 + mt*16 + g;
#pragma unroll
        for (int nt = 0; nt < 8; nt++) {
            int col = n0 + wn*64 + nt*8 + kq;
            if (SPLIT) {
                unsigned h0, l0, h1, l1;
                split2(c[mt][nt][0], c[mt][nt][1], h0, l0);
                split2(c[mt][nt][2], c[mt][nt][3], h1, l1);
                *(unsigned*)&outH[(size_t)r0*D_ + col] = h0;
                *(unsigned*)&outL[(size_t)r0*D_ + col] = l0;
                *(unsigned*)&outH[(size_t)(r0+8)*D_ + col] = h1;
                *(unsigned*)&outL[(size_t)(r0+8)*D_ + col] = l1;
            } else {
                *(float2*)&outF[(size_t)r0*D_ + col] = make_float2(c[mt][nt][0], c[mt][nt][1]);
                *(float2*)&outF[(size_t)(r0+8)*D_ + col] = make_float2(c[mt][nt][2], c[mt][nt][3]);
            }
        }
    }
}

// ---------------------------------------------------------------------------
// Kernel 4: fragment-resident flash attention (unchanged core, split output)
// ---------------------------------------------------------------------------
#define AKH 0
#define AKL 20480
#define AVH 40960
#define AVL 57856
#define ABI 74752
#define ASM_TOT 75776
#define KP  40
#define VP  264

__global__ void __launch_bounds__(256, 1)
attn_kernel(const float* __restrict__ ehr_times, const float* __restrict__ itv) {
    extern __shared__ char sm[];
    int tid = threadIdx.x;
    int wid = tid >> 5, lane = tid & 31;
    int g  = lane >> 2;
    int kq = (lane & 3) * 2;
    int h    = blockIdx.x;
    int half = blockIdx.y;
    int bp   = blockIdx.z;
    int b = bp >> 5;

    {
        const __nv_bfloat16* kh = g_kh + (size_t)(b*L_)*D_ + h*HD_;
        const __nv_bfloat16* kl = g_kl + (size_t)(b*L_)*D_ + h*HD_;
        for (int idx = tid; idx < 2048; idx += 256) {
            int r = idx >> 3, c4 = (idx & 7) * 4;
            *(uint2*)(sm + AKH + r*(KP*2) + c4*2) = *(const uint2*)(kh + r*D_ + c4);
            *(uint2*)(sm + AKL + r*(KP*2) + c4*2) = *(const uint2*)(kl + r*D_ + c4);
        }
    }
    {
        const __nv_bfloat16* vh = g_vth + (size_t)(b*D_ + h*HD_)*L_;
        const __nv_bfloat16* vl = g_vtl + (size_t)(b*D_ + h*HD_)*L_;
        for (int idx = tid; idx < 1024; idx += 256) {
            int hd = idx >> 5, c8 = (idx & 31) * 8;
            *(uint4*)(sm + AVH + hd*(VP*2) + c8*2) = *(const uint4*)(vh + hd*L_ + c8);
            *(uint4*)(sm + AVL + hd*(VP*2) + c8*2) = *(const uint4*)(vl + hd*L_ + c8);
        }
    }
    {
        float s = itv[bp*2 + 0];
        float e = itv[bp*2 + 1];
        float ctr = 0.5f*(s+e);
        float t = ehr_times[b*L_ + tid];
        ((float*)(sm + ABI))[tid] = (t >= s && t <= e) ? -fabsf(t - ctr) : -1e30f;
    }

    unsigned qah[2][4], qal[2][4];
    {
        size_t qrow = (size_t)bp*L_ + half*128 + wid*16;
#pragma unroll
        for (int kt = 0; kt < 2; kt++) {
            size_t base = (qrow + g)*D_ + h*HD_ + kt*16 + kq;
            qah[kt][0] = *(const unsigned*)(g_qh + base);
            qah[kt][1] = *(const unsigned*)(g_qh + base + 8*D_);
            qah[kt][2] = *(const unsigned*)(g_qh + base + 8);
            qah[kt][3] = *(const unsigned*)(g_qh + base + 8*D_ + 8);
            qal[kt][0] = *(const unsigned*)(g_ql + base);
            qal[kt][1] = *(const unsigned*)(g_ql + base + 8*D_);
            qal[kt][2] = *(const unsigned*)(g_ql + base + 8);
            qal[kt][3] = *(const unsigned*)(g_ql + base + 8*D_ + 8);
        }
    }
    __syncthreads();

    float c[32][4];
#pragma unroll
    for (int nt = 0; nt < 32; nt++) { c[nt][0]=0.f; c[nt][1]=0.f; c[nt][2]=0.f; c[nt][3]=0.f; }
#pragma unroll
    for (int nt = 0; nt < 32; nt++) {
        const char* kb = sm + (nt*8 + g)*(KP*2);
#pragma unroll
        for (int kt = 0; kt < 2; kt++) {
            unsigned bh[2], bl[2];
            bh[0] = *(const unsigned*)(kb + AKH + (kt*16 + kq)*2);
            bh[1] = *(const unsigned*)(kb + AKH + (kt*16 + kq)*2 + 16);
            bl[0] = *(const unsigned*)(kb + AKL + (kt*16 + kq)*2);
            bl[1] = *(const unsigned*)(kb + AKL + (kt*16 + kq)*2 + 16);
            mma16816(c[nt], qah[kt], bh);
            mma16816(c[nt], qal[kt], bh);
            mma16816(c[nt], qah[kt], bl);
        }
    }

    const float* sb = (const float*)(sm + ABI);
    float m0 = -1e30f, m1 = -1e30f;
#pragma unroll
    for (int nt = 0; nt < 32; nt++) {
        float2 bb = *(const float2*)&sb[nt*8 + kq];
        m0 = fmaxf(m0, fmaxf(c[nt][0] + bb.x, c[nt][1] + bb.y));
        m1 = fmaxf(m1, fmaxf(c[nt][2] + bb.x, c[nt][3] + bb.y));
    }
    m0 = fmaxf(m0, __shfl_xor_sync(0xffffffffu, m0, 1));
    m0 = fmaxf(m0, __shfl_xor_sync(0xffffffffu, m0, 2));
    m1 = fmaxf(m1, __shfl_xor_sync(0xffffffffu, m1, 1));
    m1 = fmaxf(m1, __shfl_xor_sync(0xffffffffu, m1, 2));
    float d0 = 0.f, d1 = 0.f;
#pragma unroll
    for (int nt = 0; nt < 32; nt++) {
        float2 bb = *(const float2*)&sb[nt*8 + kq];
        c[nt][0] = __expf(c[nt][0] + bb.x - m0);
        c[nt][1] = __expf(c[nt][1] + bb.y - m0);
        c[nt][2] = __expf(c[nt][2] + bb.x - m1);
        c[nt][3] = __expf(c[nt][3] + bb.y - m1);
        d0 += c[nt][0] + c[nt][1];
        d1 += c[nt][2] + c[nt][3];
    }
    d0 += __shfl_xor_sync(0xffffffffu, d0, 1);
    d0 += __shfl_xor_sync(0xffffffffu, d0, 2);
    d1 += __shfl_xor_sync(0xffffffffu, d1, 1);
    d1 += __shfl_xor_sync(0xffffffffu, d1, 2);

    float o[4][4];
#pragma unroll
    for (int nt = 0; nt < 4; nt++) { o[nt][0]=0.f; o[nt][1]=0.f; o[nt][2]=0.f; o[nt][3]=0.f; }
#pragma unroll
    for (int kt = 0; kt < 16; kt++) {
        unsigned ah[4], al[4];
        split2(c[2*kt][0],   c[2*kt][1],   ah[0], al[0]);
        split2(c[2*kt][2],   c[2*kt][3],   ah[1], al[1]);
        split2(c[2*kt+1][0], c[2*kt+1][1], ah[2], al[2]);
        split2(c[2*kt+1][2], c[2*kt+1][3], ah[3], al[3]);
#pragma unroll
        for (int nt = 0; nt < 4; nt++) {
            const char* vb = sm + (nt*8 + g)*(VP*2) + (kt*16 + kq)*2;
            unsigned bh[2], bl[2];
            bh[0] = *(const unsigned*)(vb + AVH);
            bh[1] = *(const unsigned*)(vb + AVH + 16);
            bl[0] = *(const unsigned*)(vb + AVL);
            bl[1] = *(const unsigned*)(vb + AVL + 16);
            mma16816(o[nt], ah, bh);
            mma16816(o[nt], al, bh);
            mma16816(o[nt], ah, bl);
        }
    }

    {
        float inv0 = 1.f / d0, inv1 = 1.f / d1;
        size_t orow = (size_t)bp*L_ + half*128 + wid*16;
#pragma unroll
        for (int nt = 0; nt < 4; nt++) {
            unsigned h0, l0, h1, l1;
            split2(o[nt][0]*inv0, o[nt][1]*inv0, h0, l0);
            split2(o[nt][2]*inv1, o[nt][3]*inv1, h1, l1);
            size_t i0 = (orow+g  )*D_ + h*HD_ + nt*8 + kq;
            size_t i1 = (orow+g+8)*D_ + h*HD_ + nt*8 + kq;
            *(unsigned*)&g_ctxh[i0] = h0;
            *(unsigned*)&g_ctxl[i0] = l0;
            *(unsigned*)&g_ctxh[i1] = h1;
            *(unsigned*)&g_ctxl[i1] = l1;
        }
    }
}

// ---------------------------------------------------------------------------
extern "C" void kernel_launch(void* const* d_in, const int* in_sizes, int n_in,
                              void* d_out, int out_size) {
    const float* ehr       = (const float*)d_in[0];
    const float* ehr_times = (const float*)d_in[1];
    const float* itv       = (const float*)d_in[2];
    const float* w1        = (const float*)d_in[3];
    const float* b1        = (const float*)d_in[4];
    const float* w2        = (const float*)d_in[5];
    const float* b2        = (const float*)d_in[6];
    const float* wq        = (const float*)d_in[7];
    const float* bq        = (const float*)d_in[8];
    const float* wk        = (const float*)d_in[9];
    const float* bk        = (const float*)d_in[10];
    const float* wv        = (const float*)d_in[11];
    const float* bv        = (const float*)d_in[12];
    const float* wo        = (const float*)d_in[13];
    const float* bo        = (const float*)d_in[14];
    float* out = (float*)d_out;

    // device-global pointers for gemm args
    __nv_bfloat16 *p_hh, *p_hl, *p_w2qTh, *p_w2qTl, *p_qh, *p_ql;
    __nv_bfloat16 *p_ctxh, *p_ctxl, *p_woTh, *p_woTl;
    float *p_bq2;
    cudaGetSymbolAddress((void**)&p_hh, g_hh);
    cudaGetSymbolAddress((void**)&p_hl, g_hl);
    cudaGetSymbolAddress((void**)&p_w2qTh, g_w2qTh);
    cudaGetSymbolAddress((void**)&p_w2qTl, g_w2qTl);
    cudaGetSymbolAddress((void**)&p_qh, g_qh);
    cudaGetSymbolAddress((void**)&p_ql, g_ql);
    cudaGetSymbolAddress((void**)&p_ctxh, g_ctxh);
    cudaGetSymbolAddress((void**)&p_ctxl, g_ctxl);
    cudaGetSymbolAddress((void**)&p_woTh, g_woTh);
    cudaGetSymbolAddress((void**)&p_woTl, g_woTl);
    cudaGetSymbolAddress((void**)&p_bq2, g_bq2);

    fuse_w_kernel<<<DH_, D_>>>(w2, wq, b2, bq);
    prep_split_kernel<<<D_, D_>>>(wo);
    kv_kernel<<<B_*L_/8, 256>>>(ehr, wk, bk, wv, bv);
    h_kernel<<<B_*P_*L_/32, 256>>>(ehr_times, itv, w1, b1);

    // q = h @ W2q' (+bq2'), split bf16 out
    gemm_kernel<DH_, true><<<dim3(256, 2), 256>>>(
        p_hh, p_hl, p_w2qTh, p_w2qTl, p_bq2, nullptr, p_qh, p_ql);

    cudaFuncSetAttribute(attn_kernel, cudaFuncAttributeMaxDynamicSharedMemorySize, ASM_TOT);
    attn_kernel<<<dim3(H_, 2, B_*P_), 256, ASM_TOT>>>(ehr_times, itv);

    // out = ctx @ wo + bo, fp32 out
    gemm_kernel<D_, false><<<dim3(256, 2), 256>>>(
        p_ctxh, p_ctxl, p_woTh, p_woTl, bo, out, nullptr, nullptr);
}

// round 8
// speedup vs baseline: 3.3209x; 1.1371x over previous
#include <cuda_runtime.h>
#include <cuda_bf16.h>
#include <math.h>
#include <cstdint>

#define B_  4
#define L_  256
#define D_  256
#define P_  32
#define H_  8
#define HD_ 32
#define DH_ 128   // D/2

// ======================= mma.sync bf16 =====================================
__device__ __forceinline__ void mma16816(float* c, const unsigned* a, const unsigned* b) {
    asm volatile("mma.sync.aligned.m16n8k16.row.col.f32.bf16.bf16.f32 "
        "{%0,%1,%2,%3}, {%4,%5,%6,%7}, {%8,%9}, {%0,%1,%2,%3};"
        : "+f"(c[0]), "+f"(c[1]), "+f"(c[2]), "+f"(c[3])
        : "r"(a[0]), "r"(a[1]), "r"(a[2]), "r"(a[3]), "r"(b[0]), "r"(b[1]));
}
__device__ __forceinline__ void split2(float x0, float x1, unsigned& whi, unsigned& wlo) {
    __nv_bfloat16 h0 = __float2bfloat16(x0);
    __nv_bfloat16 h1 = __float2bfloat16(x1);
    __nv_bfloat16 l0 = __float2bfloat16(x0 - __bfloat162float(h0));
    __nv_bfloat16 l1 = __float2bfloat16(x1 - __bfloat162float(h1));
    whi = (unsigned)*(unsigned short*)&h0 | ((unsigned)*(unsigned short*)&h1 << 16);
    wlo = (unsigned)*(unsigned short*)&l0 | ((unsigned)*(unsigned short*)&l1 << 16);
}
__device__ __forceinline__ void split1(float x, __nv_bfloat16& h, __nv_bfloat16& l) {
    h = __float2bfloat16(x);
    l = __float2bfloat16(x - __bfloat162float(h));
}

// ======================= scratch =========================================
__device__ __nv_bfloat16 g_kh[B_*L_*D_];
__device__ __nv_bfloat16 g_kl[B_*L_*D_];
__device__ __nv_bfloat16 g_vth[B_*D_*L_];       // [(b*D + c)][l]
__device__ __nv_bfloat16 g_vtl[B_*D_*L_];
__device__ __nv_bfloat16 g_qh[B_*P_*L_*D_];
__device__ __nv_bfloat16 g_ql[B_*P_*L_*D_];
__device__ __nv_bfloat16 g_ctxh[B_*P_*L_*D_];
__device__ __nv_bfloat16 g_ctxl[B_*P_*L_*D_];
__device__ __nv_bfloat16 g_hh[B_*P_*L_*DH_];
__device__ __nv_bfloat16 g_hl[B_*P_*L_*DH_];
__device__ __nv_bfloat16 g_woTh[D_*D_];         // [n][k]
__device__ __nv_bfloat16 g_woTl[D_*D_];
__device__ __nv_bfloat16 g_w2qTh[D_*DH_];       // [n][k], scale folded
__device__ __nv_bfloat16 g_w2qTl[D_*DH_];
__device__ float g_W2q[DH_*D_];
__device__ float g_bq2[D_];                     // scale folded

// ---------------------------------------------------------------------------
// Kernel 1: W2q = w2 @ wq, bq2 = scale*(b2 @ wq + bq)
// ---------------------------------------------------------------------------
__global__ void fuse_w_kernel(const float* __restrict__ w2, const float* __restrict__ wq,
                              const float* __restrict__ b2, const float* __restrict__ bq) {
    int j = blockIdx.x, c = threadIdx.x;
    float acc = 0.f;
    for (int k = 0; k < D_; k++) acc = fmaf(w2[j*D_+k], wq[k*D_+c], acc);
    g_W2q[j*D_+c] = acc;
    if (j == 0) {
        float a = 0.f;
        for (int k = 0; k < D_; k++) a = fmaf(b2[k], wq[k*D_+c], a);
        g_bq2[c] = 0.17677669529663687f * (a + bq[c]);
    }
}

// ---------------------------------------------------------------------------
// Kernel 1b: transpose+split wo and scale*W2q
// ---------------------------------------------------------------------------
__global__ void prep_split_kernel(const float* __restrict__ wo) {
    int n = blockIdx.x, k = threadIdx.x;
    __nv_bfloat16 h, l;
    split1(wo[k*D_ + n], h, l);
    g_woTh[n*D_ + k] = h;
    g_woTl[n*D_ + k] = l;
    if (k < DH_) {
        split1(0.17677669529663687f * g_W2q[k*D_ + n], h, l);
        g_w2qTh[n*DH_ + k] = h;
        g_w2qTl[n*DH_ + k] = l;
    }
}

// ---------------------------------------------------------------------------
// Kernel 2: k/v projections, emitted as bf16 hi/lo (K row-major, V transposed)
// ---------------------------------------------------------------------------
__global__ void kv_kernel(const float* __restrict__ ehr,
                          const float* __restrict__ wk, const float* __restrict__ bk,
                          const float* __restrict__ wv, const float* __restrict__ bv) {
    __shared__ float sx[8*D_];
    int row0 = blockIdx.x * 8;
    int tid = threadIdx.x;
    for (int i = tid; i < 8*D_; i += 256) sx[i] = ehr[row0*D_ + i];
    __syncthreads();
    int c = tid;
    float ak[8], av[8];
    float bkc = bk[c], bvc = bv[c];
#pragma unroll
    for (int r = 0; r < 8; r++) { ak[r] = bkc; av[r] = bvc; }
    for (int d = 0; d < D_; d++) {
        float wkd = wk[d*D_+c];
        float wvd = wv[d*D_+c];
#pragma unroll
        for (int r = 0; r < 8; r++) {
            float x = sx[r*D_+d];
            ak[r] = fmaf(x, wkd, ak[r]);
            av[r] = fmaf(x, wvd, av[r]);
        }
    }
#pragma unroll
    for (int r = 0; r < 8; r++) {
        __nv_bfloat16 h, l;
        split1(ak[r], h, l);
        g_kh[(row0+r)*D_+c] = h;
        g_kl[(row0+r)*D_+c] = l;
    }
    {
        int b  = row0 / L_;
        int l0 = row0 % L_;
        __nv_bfloat16 vh8[8], vl8[8];
#pragma unroll
        for (int r = 0; r < 8; r++) split1(av[r], vh8[r], vl8[r]);
        *(uint4*)&g_vth[(b*D_ + c)*L_ + l0] = *(uint4*)vh8;
        *(uint4*)&g_vtl[(b*D_ + c)*L_ + l0] = *(uint4*)vl8;
    }
}

// ---------------------------------------------------------------------------
// Kernel 3: time features -> MLP -> gelu -> h (split bf16)
// ---------------------------------------------------------------------------
__global__ void h_kernel(const float* __restrict__ ehr_times, const float* __restrict__ itv,
                         const float* __restrict__ w1, const float* __restrict__ b1) {
    __shared__ float3 stf[32];
    int tid = threadIdx.x;
    int g0 = blockIdx.x * 32;
    int b  = g0 / (P_*L_);
    int p  = (g0 / L_) % P_;
    int l0 = g0 % L_;
    if (tid < 32) {
        float t = ehr_times[b*L_ + l0 + tid];
        float s = itv[(b*P_+p)*2 + 0];
        float e = itv[(b*P_+p)*2 + 1];
        float ds = t - s, de = e - t;
        float x  = ds * de;
        float sg = 1.f / (1.f + expf(-x));
        stf[tid] = make_float3(ds, de, sg);
    }
    __syncthreads();
    for (int i = tid; i < 32*DH_; i += 256) {
        int r = i >> 7, j = i & 127;
        float3 tf = stf[r];
        float z = tf.x*w1[j] + tf.y*w1[DH_+j] + tf.z*w1[2*DH_+j] + b1[j];
        float v = 0.5f * z * (1.f + erff(z * 0.70710678118654752f));
        __nv_bfloat16 h, l;
        split1(v, h, l);
        g_hh[(size_t)g0*DH_ + i] = h;
        g_hl[(size_t)g0*DH_ + i] = l;
    }
}

// ---------------------------------------------------------------------------
// Generic bf16 hi/lo 3-product GEMM
// ---------------------------------------------------------------------------
template<int K, bool SPLIT>
__global__ void __launch_bounds__(256)
gemm_kernel(const __nv_bfloat16* __restrict__ Ah, const __nv_bfloat16* __restrict__ Al,
            const __nv_bfloat16* __restrict__ BTh, const __nv_bfloat16* __restrict__ BTl,
            const float* __restrict__ bias,
            float* __restrict__ outF,
            __nv_bfloat16* __restrict__ outH, __nv_bfloat16* __restrict__ outL) {
    __shared__ __nv_bfloat16 sAh[128*40], sAl[128*40], sBh[128*40], sBl[128*40];
    int tid = threadIdx.x, wid = tid >> 5, lane = tid & 31;
    int g = lane >> 2, kq = (lane & 3) * 2;
    int wm = wid & 3, wn = wid >> 2;
    int m0 = blockIdx.x * 128, n0 = blockIdx.y * 128;

    float c[2][8][4];
#pragma unroll
    for (int nt = 0; nt < 8; nt++) {
        float2 bb = *(const float2*)&bias[n0 + wn*64 + nt*8 + kq];
#pragma unroll
        for (int mt = 0; mt < 2; mt++) {
            c[mt][nt][0] = bb.x; c[mt][nt][1] = bb.y;
            c[mt][nt][2] = bb.x; c[mt][nt][3] = bb.y;
        }
    }

    for (int kc = 0; kc < K; kc += 32) {
        for (int idx = tid; idx < 1024; idx += 256) {
            int r = idx >> 3, c4 = (idx & 7) * 4;
            *(uint2*)&sAh[r*40 + c4] = *(const uint2*)&Ah[(size_t)(m0+r)*K + kc + c4];
            *(uint2*)&sAl[r*40 + c4] = *(const uint2*)&Al[(size_t)(m0+r)*K + kc + c4];
            *(uint2*)&sBh[r*40 + c4] = *(const uint2*)&BTh[(size_t)(n0+r)*K + kc + c4];
            *(uint2*)&sBl[r*40 + c4] = *(const uint2*)&BTl[(size_t)(n0+r)*K + kc + c4];
        }
        __syncthreads();
#pragma unroll
        for (int kt = 0; kt < 2; kt++) {
            unsigned ah[2][4], al[2][4];
#pragma unroll
            for (int mt = 0; mt < 2; mt++) {
                int rb = wm*32 + mt*16;
                ah[mt][0] = *(const unsigned*)&sAh[(rb+g  )*40 + kt*16 + kq];
                ah[mt][1] = *(const unsigned*)&sAh[(rb+g+8)*40 + kt*16 + kq];
                ah[mt][2] = *(const unsigned*)&sAh[(rb+g  )*40 + kt*16 + kq + 8];
                ah[mt][3] = *(const unsigned*)&sAh[(rb+g+8)*40 + kt*16 + kq + 8];
                al[mt][0] = *(const unsigned*)&sAl[(rb+g  )*40 + kt*16 + kq];
                al[mt][1] = *(const unsigned*)&sAl[(rb+g+8)*40 + kt*16 + kq];
                al[mt][2] = *(const unsigned*)&sAl[(rb+g  )*40 + kt*16 + kq + 8];
                al[mt][3] = *(const unsigned*)&sAl[(rb+g+8)*40 + kt*16 + kq + 8];
            }
#pragma unroll
            for (int nt = 0; nt < 8; nt++) {
                int rn = wn*64 + nt*8 + g;
                unsigned bh[2], bl[2];
                bh[0] = *(const unsigned*)&sBh[rn*40 + kt*16 + kq];
                bh[1] = *(const unsigned*)&sBh[rn*40 + kt*16 + kq + 8];
                bl[0] = *(const unsigned*)&sBl[rn*40 + kt*16 + kq];
                bl[1] = *(const unsigned*)&sBl[rn*40 + kt*16 + kq + 8];
#pragma unroll
                for (int mt = 0; mt < 2; mt++) {
                    mma16816(c[mt][nt], ah[mt], bh);
                    mma16816(c[mt][nt], al[mt], bh);
                    mma16816(c[mt][nt], ah[mt], bl);
                }
            }
        }
        __syncthreads();
    }

#pragma unroll
    for (int mt = 0; mt < 2; mt++) {
        int r0 = m0 + wm*32 + mt*16 + g;
#pragma unroll
        for (int nt = 0; nt < 8; nt++) {
            int col = n0 + wn*64 + nt*8 + kq;
            if (SPLIT) {
                unsigned h0, l0, h1, l1;
                split2(c[mt][nt][0], c[mt][nt][1], h0, l0);
                split2(c[mt][nt][2], c[mt][nt][3], h1, l1);
                *(unsigned*)&outH[(size_t)r0*D_ + col] = h0;
                *(unsigned*)&outL[(size_t)r0*D_ + col] = l0;
                *(unsigned*)&outH[(size_t)(r0+8)*D_ + col] = h1;
                *(unsigned*)&outL[(size_t)(r0+8)*D_ + col] = l1;
            } else {
                *(float2*)&outF[(size_t)r0*D_ + col] = make_float2(c[mt][nt][0], c[mt][nt][1]);
                *(float2*)&outF[(size_t)(r0+8)*D_ + col] = make_float2(c[mt][nt][2], c[mt][nt][3]);
            }
        }
    }
}

// ---------------------------------------------------------------------------
// Kernel 4: flash attention, online softmax over 4 key-chunks of 64.
// ---------------------------------------------------------------------------
#define AKH 0
#define AKL 20480
#define AVH 40960
#define AVL 57856
#define ABI 74752
#define ASM_TOT 75776
#define KP  40
#define VP  264

__global__ void __launch_bounds__(256, 2)
attn_kernel(const float* __restrict__ ehr_times, const float* __restrict__ itv) {
    extern __shared__ char sm[];
    int tid = threadIdx.x;
    int wid = tid >> 5, lane = tid & 31;
    int g  = lane >> 2;
    int kq = (lane & 3) * 2;
    int h    = blockIdx.x;
    int half = blockIdx.y;
    int bp   = blockIdx.z;
    int b = bp >> 5;

    {
        const __nv_bfloat16* kh = g_kh + (size_t)(b*L_)*D_ + h*HD_;
        const __nv_bfloat16* kl = g_kl + (size_t)(b*L_)*D_ + h*HD_;
        for (int idx = tid; idx < 2048; idx += 256) {
            int r = idx >> 3, c4 = (idx & 7) * 4;
            *(uint2*)(sm + AKH + r*(KP*2) + c4*2) = *(const uint2*)(kh + r*D_ + c4);
            *(uint2*)(sm + AKL + r*(KP*2) + c4*2) = *(const uint2*)(kl + r*D_ + c4);
        }
    }
    {
        const __nv_bfloat16* vh = g_vth + (size_t)(b*D_ + h*HD_)*L_;
        const __nv_bfloat16* vl = g_vtl + (size_t)(b*D_ + h*HD_)*L_;
        for (int idx = tid; idx < 1024; idx += 256) {
            int hd = idx >> 5, c8 = (idx & 31) * 8;
            *(uint4*)(sm + AVH + hd*(VP*2) + c8*2) = *(const uint4*)(vh + hd*L_ + c8);
            *(uint4*)(sm + AVL + hd*(VP*2) + c8*2) = *(const uint4*)(vl + hd*L_ + c8);
        }
    }
    {
        float s = itv[bp*2 + 0];
        float e = itv[bp*2 + 1];
        float ctr = 0.5f*(s+e);
        float t = ehr_times[b*L_ + tid];
        ((float*)(sm + ABI))[tid] = (t >= s && t <= e) ? -fabsf(t - ctr) : -1e30f;
    }

    unsigned qah[2][4], qal[2][4];
    {
        size_t qrow = (size_t)bp*L_ + half*128 + wid*16;
#pragma unroll
        for (int kt = 0; kt < 2; kt++) {
            size_t base = (qrow + g)*D_ + h*HD_ + kt*16 + kq;
            qah[kt][0] = *(const unsigned*)(g_qh + base);
            qah[kt][1] = *(const unsigned*)(g_qh + base + 8*D_);
            qah[kt][2] = *(const unsigned*)(g_qh + base + 8);
            qah[kt][3] = *(const unsigned*)(g_qh + base + 8*D_ + 8);
            qal[kt][0] = *(const unsigned*)(g_ql + base);
            qal[kt][1] = *(const unsigned*)(g_ql + base + 8*D_);
            qal[kt][2] = *(const unsigned*)(g_ql + base + 8);
            qal[kt][3] = *(const unsigned*)(g_ql + base + 8*D_ + 8);
        }
    }
    __syncthreads();

    const float* sb = (const float*)(sm + ABI);
    float m0 = -1e30f, m1 = -1e30f, d0 = 0.f, d1 = 0.f;
    float o[4][4];
#pragma unroll
    for (int nt = 0; nt < 4; nt++) { o[nt][0]=0.f; o[nt][1]=0.f; o[nt][2]=0.f; o[nt][3]=0.f; }

#pragma unroll 1
    for (int ch = 0; ch < 4; ch++) {
        // ---- S chunk = Q K^T for keys [ch*64, ch*64+64) ----
        float c[8][4];
#pragma unroll
        for (int nt = 0; nt < 8; nt++) { c[nt][0]=0.f; c[nt][1]=0.f; c[nt][2]=0.f; c[nt][3]=0.f; }
#pragma unroll
        for (int nt = 0; nt < 8; nt++) {
            const char* kb = sm + (ch*64 + nt*8 + g)*(KP*2);
#pragma unroll
            for (int kt = 0; kt < 2; kt++) {
                unsigned bh[2], bl[2];
                bh[0] = *(const unsigned*)(kb + AKH + (kt*16 + kq)*2);
                bh[1] = *(const unsigned*)(kb + AKH + (kt*16 + kq)*2 + 16);
                bl[0] = *(const unsigned*)(kb + AKL + (kt*16 + kq)*2);
                bl[1] = *(const unsigned*)(kb + AKL + (kt*16 + kq)*2 + 16);
                mma16816(c[nt], qah[kt], bh);
                mma16816(c[nt], qal[kt], bh);
                mma16816(c[nt], qah[kt], bl);
            }
        }
        // ---- add bias + chunk max ----
        float cm0 = -1e30f, cm1 = -1e30f;
#pragma unroll
        for (int nt = 0; nt < 8; nt++) {
            float2 bb = *(const float2*)&sb[ch*64 + nt*8 + kq];
            c[nt][0] += bb.x; c[nt][1] += bb.y;
            c[nt][2] += bb.x; c[nt][3] += bb.y;
            cm0 = fmaxf(cm0, fmaxf(c[nt][0], c[nt][1]));
            cm1 = fmaxf(cm1, fmaxf(c[nt][2], c[nt][3]));
        }
        cm0 = fmaxf(cm0, __shfl_xor_sync(0xffffffffu, cm0, 1));
        cm0 = fmaxf(cm0, __shfl_xor_sync(0xffffffffu, cm0, 2));
        cm1 = fmaxf(cm1, __shfl_xor_sync(0xffffffffu, cm1, 1));
        cm1 = fmaxf(cm1, __shfl_xor_sync(0xffffffffu, cm1, 2));
        // ---- online rescale ----
        float nm0 = fmaxf(m0, cm0), nm1 = fmaxf(m1, cm1);
        float corr0 = __expf(m0 - nm0), corr1 = __expf(m1 - nm1);
        m0 = nm0; m1 = nm1;
        d0 *= corr0; d1 *= corr1;
#pragma unroll
        for (int nt = 0; nt < 4; nt++) {
            o[nt][0] *= corr0; o[nt][1] *= corr0;
            o[nt][2] *= corr1; o[nt][3] *= corr1;
        }
        // ---- exp + accumulate den (per-lane partial; quad-reduced at end) ----
#pragma unroll
        for (int nt = 0; nt < 8; nt++) {
            c[nt][0] = __expf(c[nt][0] - m0);
            c[nt][1] = __expf(c[nt][1] - m0);
            c[nt][2] = __expf(c[nt][2] - m1);
            c[nt][3] = __expf(c[nt][3] - m1);
            d0 += c[nt][0] + c[nt][1];
            d1 += c[nt][2] + c[nt][3];
        }
        // ---- O += P_chunk * V_chunk ----
#pragma unroll
        for (int kt = 0; kt < 4; kt++) {
            unsigned ah[4], al[4];
            split2(c[2*kt][0],   c[2*kt][1],   ah[0], al[0]);
            split2(c[2*kt][2],   c[2*kt][3],   ah[1], al[1]);
            split2(c[2*kt+1][0], c[2*kt+1][1], ah[2], al[2]);
            split2(c[2*kt+1][2], c[2*kt+1][3], ah[3], al[3]);
#pragma unroll
            for (int nt = 0; nt < 4; nt++) {
                const char* vb = sm + (nt*8 + g)*(VP*2) + (ch*64 + kt*16 + kq)*2;
                unsigned bh[2], bl[2];
                bh[0] = *(const unsigned*)(vb + AVH);
                bh[1] = *(const unsigned*)(vb + AVH + 16);
                bl[0] = *(const unsigned*)(vb + AVL);
                bl[1] = *(const unsigned*)(vb + AVL + 16);
                mma16816(o[nt], ah, bh);
                mma16816(o[nt], al, bh);
                mma16816(o[nt], ah, bl);
            }
        }
    }

    // ---- FIX: reduce den partials across the quad (m is quad-uniform) ----
    d0 += __shfl_xor_sync(0xffffffffu, d0, 1);
    d0 += __shfl_xor_sync(0xffffffffu, d0, 2);
    d1 += __shfl_xor_sync(0xffffffffu, d1, 1);
    d1 += __shfl_xor_sync(0xffffffffu, d1, 2);

    // ---- epilogue: normalize, split, store ctx ----
    {
        float inv0 = 1.f / d0, inv1 = 1.f / d1;
        size_t orow = (size_t)bp*L_ + half*128 + wid*16;
#pragma unroll
        for (int nt = 0; nt < 4; nt++) {
            unsigned h0, l0, h1, l1;
            split2(o[nt][0]*inv0, o[nt][1]*inv0, h0, l0);
            split2(o[nt][2]*inv1, o[nt][3]*inv1, h1, l1);
            size_t i0 = (orow+g  )*D_ + h*HD_ + nt*8 + kq;
            size_t i1 = (orow+g+8)*D_ + h*HD_ + nt*8 + kq;
            *(unsigned*)&g_ctxh[i0] = h0;
            *(unsigned*)&g_ctxl[i0] = l0;
            *(unsigned*)&g_ctxh[i1] = h1;
            *(unsigned*)&g_ctxl[i1] = l1;
        }
    }
}

// ---------------------------------------------------------------------------
extern "C" void kernel_launch(void* const* d_in, const int* in_sizes, int n_in,
                              void* d_out, int out_size) {
    const float* ehr       = (const float*)d_in[0];
    const float* ehr_times = (const float*)d_in[1];
    const float* itv       = (const float*)d_in[2];
    const float* w1        = (const float*)d_in[3];
    const float* b1        = (const float*)d_in[4];
    const float* w2        = (const float*)d_in[5];
    const float* b2        = (const float*)d_in[6];
    const float* wq        = (const float*)d_in[7];
    const float* bq        = (const float*)d_in[8];
    const float* wk        = (const float*)d_in[9];
    const float* bk        = (const float*)d_in[10];
    const float* wv        = (const float*)d_in[11];
    const float* bv        = (const float*)d_in[12];
    const float* wo        = (const float*)d_in[13];
    const float* bo        = (const float*)d_in[14];
    float* out = (float*)d_out;

    __nv_bfloat16 *p_hh, *p_hl, *p_w2qTh, *p_w2qTl, *p_qh, *p_ql;
    __nv_bfloat16 *p_ctxh, *p_ctxl, *p_woTh, *p_woTl;
    float *p_bq2;
    cudaGetSymbolAddress((void**)&p_hh, g_hh);
    cudaGetSymbolAddress((void**)&p_hl, g_hl);
    cudaGetSymbolAddress((void**)&p_w2qTh, g_w2qTh);
    cudaGetSymbolAddress((void**)&p_w2qTl, g_w2qTl);
    cudaGetSymbolAddress((void**)&p_qh, g_qh);
    cudaGetSymbolAddress((void**)&p_ql, g_ql);
    cudaGetSymbolAddress((void**)&p_ctxh, g_ctxh);
    cudaGetSymbolAddress((void**)&p_ctxl, g_ctxl);
    cudaGetSymbolAddress((void**)&p_woTh, g_woTh);
    cudaGetSymbolAddress((void**)&p_woTl, g_woTl);
    cudaGetSymbolAddress((void**)&p_bq2, g_bq2);

    fuse_w_kernel<<<DH_, D_>>>(w2, wq, b2, bq);
    prep_split_kernel<<<D_, D_>>>(wo);
    kv_kernel<<<B_*L_/8, 256>>>(ehr, wk, bk, wv, bv);
    h_kernel<<<B_*P_*L_/32, 256>>>(ehr_times, itv, w1, b1);

    gemm_kernel<DH_, true><<<dim3(256, 2), 256>>>(
        p_hh, p_hl, p_w2qTh, p_w2qTl, p_bq2, nullptr, p_qh, p_ql);

    cudaFuncSetAttribute(attn_kernel, cudaFuncAttributeMaxDynamicSharedMemorySize, ASM_TOT);
    attn_kernel<<<dim3(H_, 2, B_*P_), 256, ASM_TOT>>>(ehr_times, itv);

    gemm_kernel<D_, false><<<dim3(256, 2), 256>>>(
        p_ctxh, p_ctxl, p_woTh, p_woTl, bo, out, nullptr, nullptr);
}